// round 4
// baseline (speedup 1.0000x reference)
#include <cuda_runtime.h>
#include <cstdint>
#include <cstddef>

#define BB 128
#define NN 400
#define FF 128
#define KNN 5
#define BN (BB * NN)   // 51200

typedef unsigned long long u64;

// ---------------- device scratch ----------------
__device__ float g_sq[BN];
__device__ unsigned int g_Abits[(size_t)BN * 16];  // 400-bit adjacency rows, 3.3MB
__device__ float g_m[(size_t)BN * FF];
__device__ float g_h[(size_t)BN * FF];

// ---------------- f32x2 helpers ----------------
__device__ __forceinline__ u64 dup_f32(float x) {
    u64 d; asm("mov.b64 %0,{%1,%1};" : "=l"(d) : "f"(x)); return d;
}
__device__ __forceinline__ void fma2(u64& d, u64 a, u64 b) {
    asm("fma.rn.f32x2 %0,%1,%2,%0;" : "+l"(d) : "l"(a), "l"(b));
}
__device__ __forceinline__ float2 unpack2(u64 v) {
    float2 r; asm("mov.b64 {%0,%1},%2;" : "=f"(r.x), "=f"(r.y) : "l"(v)); return r;
}

// ---------------- squared norms ----------------
__global__ void sq_kernel(const float* __restrict__ x) {
    int row = blockIdx.x * 4 + (threadIdx.x >> 5);
    int lane = threadIdx.x & 31;
    float4 v = *(const float4*)(x + (size_t)row * FF + lane * 4);
    float s = v.x * v.x + v.y * v.y + v.z * v.z + v.w * v.w;
#pragma unroll
    for (int o = 16; o; o >>= 1) s += __shfl_xor_sync(0xffffffffu, s, o);
    if (lane == 0) g_sq[row] = s;
}

// ---------------- fused distance + top-5 + adjacency scatter ----------------
#define KNN_SMEM ((128 * 64 + 128 * 128 + 416 + 64 * 5 * 2 + 8 * 5 * 2) * 4)

__global__ void __launch_bounds__(256, 2) knn_kernel(const float* __restrict__ x) {
    extern __shared__ float sm[];
    float* s_xiT = sm;                      // 128k x 64 rows (k-major, swizzled &15)
    float* s_xjT = s_xiT + 128 * 64;        // 128k x 128 rows (swizzled &31)
    float* s_sq  = s_xjT + 128 * 128;       // 416
    float* s_bv  = s_sq + 416;              // 64 x 5 running top-5 values (sorted)
    int*   s_bi  = (int*)(s_bv + 64 * 5);   // 64 x 5 running top-5 indices
    float* s_tv  = (float*)(s_bi + 64 * 5); // 8 x 5 per-warp tile scratch
    int*   s_ti  = (int*)(s_tv + 8 * 5);    // 8 x 5

    const int b  = blockIdx.y;
    const int i0 = blockIdx.x * 64;
    const int t  = threadIdx.x;
    const int tx = t & 31, ty = t >> 5;
    const int lane = t & 31;
    const float INF = __int_as_float(0x7f800000);
    const float* xb = x + (size_t)b * NN * FF;

    for (int j = t; j < NN; j += 256) s_sq[j] = g_sq[b * NN + j];
    for (int q = t; q < 64 * KNN; q += 256) { s_bv[q] = INF; s_bi[q] = 0x7fffffff; }

    // load xi tile: 64 rows x 128 k, k-major, swizzle &15
    for (int idx = t; idx < 512; idx += 256) {
        int ob = idx >> 5, kc = idx & 31;
        float vv[4][4];
#pragma unroll
        for (int r = 0; r < 4; r++) {
            int ir = i0 + ob * 4 + r;
            float4 v = (ir < NN) ? *(const float4*)(xb + (size_t)ir * FF + kc * 4)
                                 : make_float4(0.f, 0.f, 0.f, 0.f);
            vv[r][0] = v.x; vv[r][1] = v.y; vv[r][2] = v.z; vv[r][3] = v.w;
        }
#pragma unroll
        for (int c = 0; c < 4; c++)
            *(float4*)&s_xiT[(kc * 4 + c) * 64 + (((ob ^ kc) & 15) << 2)] =
                make_float4(vv[0][c], vv[1][c], vv[2][c], vv[3][c]);
    }

    for (int j0 = 0; j0 < NN; j0 += 128) {
        __syncthreads();
        // load xj tile: 128 rows x 128 k
        for (int idx = t; idx < 1024; idx += 256) {
            int ob = idx >> 5, kc = idx & 31;
            float vv[4][4];
#pragma unroll
            for (int r = 0; r < 4; r++) {
                int jr = j0 + ob * 4 + r;
                float4 v = (jr < NN) ? *(const float4*)(xb + (size_t)jr * FF + kc * 4)
                                     : make_float4(0.f, 0.f, 0.f, 0.f);
                vv[r][0] = v.x; vv[r][1] = v.y; vv[r][2] = v.z; vv[r][3] = v.w;
            }
#pragma unroll
            for (int c = 0; c < 4; c++)
                *(float4*)&s_xjT[(kc * 4 + c) * 128 + (((ob ^ kc) & 31) << 2)] =
                    make_float4(vv[0][c], vv[1][c], vv[2][c], vv[3][c]);
        }
        __syncthreads();

        // acc2[rp][c]: row pair (2rp, 2rp+1) of this thread's 8 rows, col c
        u64 acc2[4][4] = {};
#pragma unroll
        for (int k4 = 0; k4 < 32; k4++) {
            const float* a0 = &s_xiT[(k4 * 4) * 64 + ((((2 * ty)     ^ k4) & 15) << 2)];
            const float* a1 = &s_xiT[(k4 * 4) * 64 + ((((2 * ty + 1) ^ k4) & 15) << 2)];
            const float* bb = &s_xjT[(k4 * 4) * 128 + (((tx ^ k4) & 31) << 2)];
#pragma unroll
            for (int kk = 0; kk < 4; kk++) {
                float4 bv = *(const float4*)(bb + kk * 128);
                u64 bd0 = dup_f32(bv.x), bd1 = dup_f32(bv.y), bd2 = dup_f32(bv.z), bd3 = dup_f32(bv.w);
                ulonglong2 av0 = *(const ulonglong2*)(a0 + kk * 64);
                ulonglong2 av1 = *(const ulonglong2*)(a1 + kk * 64);
                fma2(acc2[0][0], av0.x, bd0); fma2(acc2[0][1], av0.x, bd1);
                fma2(acc2[0][2], av0.x, bd2); fma2(acc2[0][3], av0.x, bd3);
                fma2(acc2[1][0], av0.y, bd0); fma2(acc2[1][1], av0.y, bd1);
                fma2(acc2[1][2], av0.y, bd2); fma2(acc2[1][3], av0.y, bd3);
                fma2(acc2[2][0], av1.x, bd0); fma2(acc2[2][1], av1.x, bd1);
                fma2(acc2[2][2], av1.x, bd2); fma2(acc2[2][3], av1.x, bd3);
                fma2(acc2[3][0], av1.y, bd0); fma2(acc2[3][1], av1.y, bd1);
                fma2(acc2[3][2], av1.y, bd2); fma2(acc2[3][3], av1.y, bd3);
            }
        }

        // scores: row i0+ty*8+rr, col j0+tx*4+c
        float scv[8][4];
#pragma unroll
        for (int rp = 0; rp < 4; rp++)
#pragma unroll
            for (int c = 0; c < 4; c++) {
                int jg = j0 + tx * 4 + c;
                float2 p = unpack2(acc2[rp][c]);
                float sq = (jg < NN) ? s_sq[jg] : 0.f;
                scv[2 * rp][c]     = (jg < NN) ? sq - 2.f * p.x : INF;
                scv[2 * rp + 1][c] = (jg < NN) ? sq - 2.f * p.y : INF;
            }

        // per-row top-5 of tile with early exit vs running 5th-best
#pragma unroll
        for (int rr = 0; rr < 8; rr++) {
            int li = ty * 8 + rr;
            int irow = i0 + li;                  // warp-uniform
            if (irow < NN) {
                float kv = s_bv[li * KNN + 4];
                int   ki = s_bi[li * KNN + 4];
                bool cand = false;
#pragma unroll
                for (int c = 0; c < 4; c++) {
                    float v = scv[rr][c];
                    int jg = j0 + tx * 4 + c;
                    cand |= (v < kv) || (v == kv && jg < ki);
                }
                if (__ballot_sync(0xffffffffu, cand)) {
                    if (lane < KNN) { s_tv[ty * KNN + lane] = INF; s_ti[ty * KNN + lane] = 0x7fffffff; }
                    __syncwarp();
                    for (int q = 0; q < KNN; q++) {
                        float bv = scv[rr][0]; int bc = 0;
                        if (scv[rr][1] < bv) { bv = scv[rr][1]; bc = 1; }
                        if (scv[rr][2] < bv) { bv = scv[rr][2]; bc = 2; }
                        if (scv[rr][3] < bv) { bv = scv[rr][3]; bc = 3; }
                        int bj = j0 + tx * 4 + bc;
#pragma unroll
                        for (int o = 16; o; o >>= 1) {
                            float ov = __shfl_xor_sync(0xffffffffu, bv, o);
                            int   oj = __shfl_xor_sync(0xffffffffu, bj, o);
                            if (ov < bv || (ov == bv && oj < bj)) { bv = ov; bj = oj; }
                        }
                        bool beats = (bv < kv) || (bv == kv && bj < ki);   // uniform
                        if (!beats) break;
                        if (lane == 0) { s_tv[ty * KNN + q] = bv; s_ti[ty * KNN + q] = bj; }
                        int lc = bj - j0 - tx * 4;
                        if (lc == 0) scv[rr][0] = INF;
                        if (lc == 1) scv[rr][1] = INF;
                        if (lc == 2) scv[rr][2] = INF;
                        if (lc == 3) scv[rr][3] = INF;
                    }
                    __syncwarp();
                    if (lane == 0) {
                        float rv[KNN]; int ri[KNN];
                        float* av = &s_bv[li * KNN]; int* ai = &s_bi[li * KNN];
                        float* tv = &s_tv[ty * KNN]; int* ti = &s_ti[ty * KNN];
                        int p = 0, q = 0;
#pragma unroll
                        for (int o = 0; o < KNN; o++) {
                            float va = av[p], vt = tv[q];
                            bool takeA = (va < vt) || (va == vt && ai[p] < ti[q]);
                            if (takeA) { rv[o] = va; ri[o] = ai[p]; p++; }
                            else       { rv[o] = vt; ri[o] = ti[q]; q++; }
                        }
#pragma unroll
                        for (int o = 0; o < KNN; o++) { av[o] = rv[o]; ai[o] = ri[o]; }
                    }
                    __syncwarp();
                }
            }
        }
    }
    __syncthreads();

    // scatter symmetric adjacency bits
    if (t < 64) {
        int il = i0 + t;
        if (il < NN) {
            size_t gi = (size_t)(b * NN + il);
#pragma unroll
            for (int q = 0; q < KNN; q++) {
                int j = s_bi[t * KNN + q];
                atomicOr(&g_Abits[gi * 16 + (j >> 5)], 1u << (j & 31));
                atomicOr(&g_Abits[((size_t)(b * NN + j)) * 16 + (il >> 5)], 1u << (il & 31));
            }
        }
    }
}

// ---------------- mean aggregation: 1 warp per node, bitmask scan ----------------
__global__ void agg_kernel(const float* __restrict__ src, float* __restrict__ dst) {
    __shared__ short s_list[4][NN];
    int w = threadIdx.x >> 5, lane = threadIdx.x & 31;
    int node = blockIdx.x * 4 + w;
    int b = node / NN;
    const unsigned int* Arow = g_Abits + (size_t)node * 16;
    unsigned int m = (lane < 13) ? Arow[lane] : 0u;
    int c = __popc(m);
    int s = c;
#pragma unroll
    for (int o = 1; o < 32; o <<= 1) {
        int v = __shfl_up_sync(0xffffffffu, s, o);
        if (lane >= o) s += v;
    }
    int base = s - c;
    int total = __shfl_sync(0xffffffffu, s, 31);
    unsigned int mm = m; int kpos = 0;
    while (mm) {
        int bit = __ffs(mm) - 1;
        s_list[w][base + kpos] = (short)(lane * 32 + bit);
        kpos++; mm &= mm - 1;
    }
    __syncwarp();
    const float* sb = src + (size_t)b * NN * FF;
    float4 acc = make_float4(0.f, 0.f, 0.f, 0.f);
    for (int e = 0; e < total; e++) {
        float4 v = *(const float4*)(sb + (size_t)s_list[w][e] * FF + lane * 4);
        acc.x += v.x; acc.y += v.y; acc.z += v.z; acc.w += v.w;
    }
    float d = (float)total;
    float4 o = make_float4(acc.x / d, acc.y / d, acc.z / d, acc.w / d);
    *(float4*)(dst + (size_t)node * FF + lane * 4) = o;
}

// ---------------- fused dual-GEMM: out = act( Xa@Wa^T + Xb@Wb^T + bias ) ----------------
#define GEMM_SMEM ((64 * 128 + 64 * 128) * 4)

template <bool RELU>
__global__ void __launch_bounds__(256, 2) gemm_kernel(
        const float* __restrict__ Xa, const float* __restrict__ Wa,
        const float* __restrict__ Xb, const float* __restrict__ Wb,
        const float* __restrict__ bias, float* __restrict__ out) {
    extern __shared__ float sm2[];
    float* s_A = sm2;              // 64k x 128 rows (k-major, swizzled &31)
    float* s_B = sm2 + 64 * 128;   // 64k x 128 cols
    const int r0 = blockIdx.x * 128;
    const int t  = threadIdx.x;
    const int tx = t & 31, ty = t >> 5;    // cols tx*4, rows ty*16..+15
    // acc2[rp][c]: row pair (2rp, 2rp+1), col c
    u64 acc2[8][4] = {};

#pragma unroll
    for (int ch = 0; ch < 4; ch++) {
        const float* X = (ch < 2) ? Xa : Xb;
        const float* W = (ch < 2) ? Wa : Wb;
        const int koff = (ch & 1) * 64;
        if (ch) __syncthreads();
        // load X chunk: 128 rows x 64 k
#pragma unroll
        for (int idx0 = 0; idx0 < 512; idx0 += 256) {
            int idx = idx0 + t;
            int ob = idx >> 4, kc = idx & 15;
            float vv[4][4];
#pragma unroll
            for (int r = 0; r < 4; r++) {
                float4 v = *(const float4*)(X + (size_t)(r0 + ob * 4 + r) * FF + koff + kc * 4);
                vv[r][0] = v.x; vv[r][1] = v.y; vv[r][2] = v.z; vv[r][3] = v.w;
            }
#pragma unroll
            for (int c = 0; c < 4; c++)
                *(float4*)&s_A[(kc * 4 + c) * 128 + (((ob ^ kc) & 31) << 2)] =
                    make_float4(vv[0][c], vv[1][c], vv[2][c], vv[3][c]);
        }
        // load W chunk: 128 out-cols x 64 k
#pragma unroll
        for (int idx0 = 0; idx0 < 512; idx0 += 256) {
            int idx = idx0 + t;
            int ob = idx >> 4, kc = idx & 15;
            float vv[4][4];
#pragma unroll
            for (int r = 0; r < 4; r++) {
                float4 v = *(const float4*)(W + (size_t)(ob * 4 + r) * FF + koff + kc * 4);
                vv[r][0] = v.x; vv[r][1] = v.y; vv[r][2] = v.z; vv[r][3] = v.w;
            }
#pragma unroll
            for (int c = 0; c < 4; c++)
                *(float4*)&s_B[(kc * 4 + c) * 128 + (((ob ^ kc) & 31) << 2)] =
                    make_float4(vv[0][c], vv[1][c], vv[2][c], vv[3][c]);
        }
        __syncthreads();

#pragma unroll
        for (int k4 = 0; k4 < 16; k4++) {
            const float* bb = &s_B[(k4 * 4) * 128 + (((tx ^ k4) & 31) << 2)];
            const float* a0 = &s_A[(k4 * 4) * 128 + ((((4 * ty + 0) ^ k4) & 31) << 2)];
            const float* a1 = &s_A[(k4 * 4) * 128 + ((((4 * ty + 1) ^ k4) & 31) << 2)];
            const float* a2 = &s_A[(k4 * 4) * 128 + ((((4 * ty + 2) ^ k4) & 31) << 2)];
            const float* a3 = &s_A[(k4 * 4) * 128 + ((((4 * ty + 3) ^ k4) & 31) << 2)];
#pragma unroll
            for (int kk = 0; kk < 4; kk++) {
                float4 bv = *(const float4*)(bb + kk * 128);
                u64 bd0 = dup_f32(bv.x), bd1 = dup_f32(bv.y), bd2 = dup_f32(bv.z), bd3 = dup_f32(bv.w);
                ulonglong2 av0 = *(const ulonglong2*)(a0 + kk * 128);
                ulonglong2 av1 = *(const ulonglong2*)(a1 + kk * 128);
                ulonglong2 av2 = *(const ulonglong2*)(a2 + kk * 128);
                ulonglong2 av3 = *(const ulonglong2*)(a3 + kk * 128);
                fma2(acc2[0][0], av0.x, bd0); fma2(acc2[0][1], av0.x, bd1);
                fma2(acc2[0][2], av0.x, bd2); fma2(acc2[0][3], av0.x, bd3);
                fma2(acc2[1][0], av0.y, bd0); fma2(acc2[1][1], av0.y, bd1);
                fma2(acc2[1][2], av0.y, bd2); fma2(acc2[1][3], av0.y, bd3);
                fma2(acc2[2][0], av1.x, bd0); fma2(acc2[2][1], av1.x, bd1);
                fma2(acc2[2][2], av1.x, bd2); fma2(acc2[2][3], av1.x, bd3);
                fma2(acc2[3][0], av1.y, bd0); fma2(acc2[3][1], av1.y, bd1);
                fma2(acc2[3][2], av1.y, bd2); fma2(acc2[3][3], av1.y, bd3);
                fma2(acc2[4][0], av2.x, bd0); fma2(acc2[4][1], av2.x, bd1);
                fma2(acc2[4][2], av2.x, bd2); fma2(acc2[4][3], av2.x, bd3);
                fma2(acc2[5][0], av2.y, bd0); fma2(acc2[5][1], av2.y, bd1);
                fma2(acc2[5][2], av2.y, bd2); fma2(acc2[5][3], av2.y, bd3);
                fma2(acc2[6][0], av3.x, bd0); fma2(acc2[6][1], av3.x, bd1);
                fma2(acc2[6][2], av3.x, bd2); fma2(acc2[6][3], av3.x, bd3);
                fma2(acc2[7][0], av3.y, bd0); fma2(acc2[7][1], av3.y, bd1);
                fma2(acc2[7][2], av3.y, bd2); fma2(acc2[7][3], av3.y, bd3);
            }
        }
    }

    float4 bv4 = *(const float4*)(bias + tx * 4);
    float bb4[4] = {bv4.x, bv4.y, bv4.z, bv4.w};
#pragma unroll
    for (int rp = 0; rp < 8; rp++) {
        float2 p[4];
#pragma unroll
        for (int c = 0; c < 4; c++) p[c] = unpack2(acc2[rp][c]);
        float4 o0, o1;
        float* e0 = (float*)&o0; float* e1 = (float*)&o1;
#pragma unroll
        for (int c = 0; c < 4; c++) {
            float v0 = p[c].x + bb4[c];
            float v1 = p[c].y + bb4[c];
            if (RELU) { v0 = fmaxf(v0, 0.f); v1 = fmaxf(v1, 0.f); }
            e0[c] = v0; e1[c] = v1;
        }
        int row = r0 + ty * 16 + 2 * rp;
        *(float4*)(out + (size_t)row * FF + tx * 4) = o0;
        *(float4*)(out + (size_t)(row + 1) * FF + tx * 4) = o1;
    }
}

// ---------------- launch ----------------
extern "C" void kernel_launch(void* const* d_in, const int* in_sizes, int n_in,
                              void* d_out, int out_size) {
    const float* x   = (const float*)d_in[0];
    const float* W1l = (const float*)d_in[1];
    const float* b1l = (const float*)d_in[2];
    const float* W1r = (const float*)d_in[3];
    const float* W2l = (const float*)d_in[4];
    const float* b2l = (const float*)d_in[5];
    const float* W2r = (const float*)d_in[6];
    float* out = (float*)d_out;

    void* aptr = nullptr;
    cudaGetSymbolAddress(&aptr, g_Abits);
    float* mp = nullptr; cudaGetSymbolAddress((void**)&mp, g_m);
    float* hp = nullptr; cudaGetSymbolAddress((void**)&hp, g_h);

    cudaFuncSetAttribute(knn_kernel, cudaFuncAttributeMaxDynamicSharedMemorySize, KNN_SMEM);
    cudaFuncSetAttribute(gemm_kernel<true>,  cudaFuncAttributeMaxDynamicSharedMemorySize, GEMM_SMEM);
    cudaFuncSetAttribute(gemm_kernel<false>, cudaFuncAttributeMaxDynamicSharedMemorySize, GEMM_SMEM);

    cudaMemsetAsync(aptr, 0, (size_t)BN * 16 * sizeof(unsigned int), 0);
    sq_kernel<<<BN / 4, 128>>>(x);
    dim3 kg(7, BB);
    knn_kernel<<<kg, 256, KNN_SMEM>>>(x);
    agg_kernel<<<BN / 4, 128>>>(x, mp);
    gemm_kernel<true><<<BN / 128, 256, GEMM_SMEM>>>(mp, W1l, x, W1r, b1l, hp);
    agg_kernel<<<BN / 4, 128>>>(hp, mp);
    gemm_kernel<false><<<BN / 128, 256, GEMM_SMEM>>>(mp, W2l, hp, W2r, b2l, out);
}